// round 4
// baseline (speedup 1.0000x reference)
#include <cuda_runtime.h>

#define BB 16
#define CC 32
#define HH 384
#define WW 384
#define NKK 32
#define HID 128
#define HWD (HH * WW)
#define NPLANES (BB * NKK)   // 512
#define NOUT (NKK * 9)       // 288

// Scratch (no device allocation allowed): pooled means + generated kernels
__device__ float g_pooled[BB * CC];          // 512 floats
__device__ float g_kernels[BB * NKK * 9];    // 4608 floats

// ---------------------------------------------------------------------------
// Kernel 1: per-(b,c) global average pool. One block per plane.
// ---------------------------------------------------------------------------
__global__ __launch_bounds__(256) void pool_kernel(const float* __restrict__ x) {
    const int plane = blockIdx.x;
    const float4* p4 = reinterpret_cast<const float4*>(x + (size_t)plane * HWD);
    const int n4 = HWD / 4;  // 36864

    float s = 0.0f;
    for (int i = threadIdx.x; i < n4; i += 256) {
        float4 v = __ldg(&p4[i]);
        s += (v.x + v.y) + (v.z + v.w);
    }
    // warp reduce
    #pragma unroll
    for (int o = 16; o; o >>= 1) s += __shfl_down_sync(0xffffffffu, s, o);

    __shared__ float ws[8];
    const int lane = threadIdx.x & 31;
    const int wid  = threadIdx.x >> 5;
    if (lane == 0) ws[wid] = s;
    __syncthreads();
    if (wid == 0) {
        s = (lane < 8) ? ws[lane] : 0.0f;
        #pragma unroll
        for (int o = 4; o; o >>= 1) s += __shfl_down_sync(0xffffffffu, s, o);
        if (lane == 0) g_pooled[plane] = s * (1.0f / (float)HWD);
    }
}

// ---------------------------------------------------------------------------
// Kernel 2: tiny MLP: pooled[16,32] -> relu(.@w1+b1)[16,128] -> (.@w2+b2)[16,288]
// One block, 256 threads. Everything staged in smem.
// ---------------------------------------------------------------------------
__global__ __launch_bounds__(256) void mlp_kernel(const float* __restrict__ w1,
                                                  const float* __restrict__ b1,
                                                  const float* __restrict__ w2,
                                                  const float* __restrict__ b2) {
    __shared__ float ps[BB * CC];    // 512
    __shared__ float hs[BB * HID];   // 2048
    const int tid = threadIdx.x;

    for (int i = tid; i < BB * CC; i += 256) ps[i] = g_pooled[i];
    __syncthreads();

    // hidden layer: 16*128 = 2048 outputs
    for (int idx = tid; idx < BB * HID; idx += 256) {
        const int b = idx / HID, j = idx % HID;
        float s = b1[j];
        #pragma unroll
        for (int c = 0; c < CC; c++) s += ps[b * CC + c] * w1[c * HID + j];
        hs[idx] = fmaxf(s, 0.0f);
    }
    __syncthreads();

    // output layer: 16*288 = 4608 outputs
    for (int idx = tid; idx < BB * NOUT; idx += 256) {
        const int b = idx / NOUT, o = idx % NOUT;
        float s = b2[o];
        #pragma unroll 8
        for (int j = 0; j < HID; j++) s += hs[b * HID + j] * w2[j * NOUT + o];
        g_kernels[idx] = s;
    }
}

// ---------------------------------------------------------------------------
// Kernel 3: per-plane dynamic depthwise 3x3, zero padding.
// Block (96,4): tx covers full width (96*4=384) with float4; each thread
// computes a 4-row x 4-col register tile using a 3-row sliding window.
// 6 row-loads (1x LDG.128 + 2 scalar edge LDGs) per 16 outputs.
// ---------------------------------------------------------------------------
__device__ __forceinline__ void load_row6(const float* __restrict__ xp, int r,
                                          int cb, int tx, float a[6]) {
    if (r < 0 || r >= HH) {
        #pragma unroll
        for (int i = 0; i < 6; i++) a[i] = 0.0f;
        return;
    }
    const float* rp = xp + r * WW + cb;
    const float4 c = *reinterpret_cast<const float4*>(rp);
    a[0] = (tx > 0) ? __ldg(rp - 1) : 0.0f;
    a[1] = c.x; a[2] = c.y; a[3] = c.z; a[4] = c.w;
    a[5] = (tx < (WW / 4 - 1)) ? __ldg(rp + 4) : 0.0f;
}

__global__ __launch_bounds__(384) void conv_kernel(const float* __restrict__ x,
                                                   float* __restrict__ out) {
    const int plane = blockIdx.x;                 // b*NK + nk  (C == NK)
    const int tx = threadIdx.x;                   // 0..95
    const int ty = threadIdx.y;                   // 0..3
    const int cb = tx * 4;
    const int r0 = blockIdx.y * 16 + ty * 4;

    const float* xp = x   + (size_t)plane * HWD;
    float*       op = out + (size_t)plane * HWD;

    const float* kw = g_kernels + plane * 9;
    const float w00 = kw[0], w01 = kw[1], w02 = kw[2];
    const float w10 = kw[3], w11 = kw[4], w12 = kw[5];
    const float w20 = kw[6], w21 = kw[7], w22 = kw[8];

    float a0[6], a1[6], a2[6];
    load_row6(xp, r0 - 1, cb, tx, a0);
    load_row6(xp, r0,     cb, tx, a1);

    #pragma unroll
    for (int i = 0; i < 4; i++) {
        load_row6(xp, r0 + i + 1, cb, tx, a2);

        float4 o;
        o.x = w00 * a0[0] + w01 * a0[1] + w02 * a0[2]
            + w10 * a1[0] + w11 * a1[1] + w12 * a1[2]
            + w20 * a2[0] + w21 * a2[1] + w22 * a2[2];
        o.y = w00 * a0[1] + w01 * a0[2] + w02 * a0[3]
            + w10 * a1[1] + w11 * a1[2] + w12 * a1[3]
            + w20 * a2[1] + w21 * a2[2] + w22 * a2[3];
        o.z = w00 * a0[2] + w01 * a0[3] + w02 * a0[4]
            + w10 * a1[2] + w11 * a1[3] + w12 * a1[4]
            + w20 * a2[2] + w21 * a2[3] + w22 * a2[4];
        o.w = w00 * a0[3] + w01 * a0[4] + w02 * a0[5]
            + w10 * a1[3] + w11 * a1[4] + w12 * a1[5]
            + w20 * a2[3] + w21 * a2[4] + w22 * a2[5];

        *reinterpret_cast<float4*>(op + (r0 + i) * WW + cb) = o;

        #pragma unroll
        for (int k = 0; k < 6; k++) { a0[k] = a1[k]; a1[k] = a2[k]; }
    }
}

// ---------------------------------------------------------------------------
extern "C" void kernel_launch(void* const* d_in, const int* in_sizes, int n_in,
                              void* d_out, int out_size) {
    const float* x  = (const float*)d_in[0];
    const float* w1 = (const float*)d_in[1];
    const float* b1 = (const float*)d_in[2];
    const float* w2 = (const float*)d_in[3];
    const float* b2 = (const float*)d_in[4];
    float* out = (float*)d_out;

    pool_kernel<<<NPLANES, 256>>>(x);
    mlp_kernel<<<1, 256>>>(w1, b1, w2, b2);
    conv_kernel<<<dim3(NPLANES, HH / 16), dim3(96, 4)>>>(x, out);
}

// round 5
// speedup vs baseline: 1.0214x; 1.0214x over previous
#include <cuda_runtime.h>

#define BB 16
#define CC 32
#define HH 384
#define WW 384
#define NKK 32
#define HID 128
#define HWD (HH * WW)
#define NPLANES (BB * NKK)   // 512
#define NOUT (NKK * 9)       // 288

// Scratch (no device allocation allowed): pooled means + generated kernels
__device__ float g_pooled[BB * CC];          // 512 floats
__device__ float g_kernels[BB * NKK * 9];    // 4608 floats

// ---------------------------------------------------------------------------
// Kernel 1: per-(b,c) global average pool. One block per plane.
// Measured at 81% DRAM / 6428 GB/s -- at roofline, unchanged.
// ---------------------------------------------------------------------------
__global__ __launch_bounds__(256) void pool_kernel(const float* __restrict__ x) {
    const int plane = blockIdx.x;
    const float4* p4 = reinterpret_cast<const float4*>(x + (size_t)plane * HWD);
    const int n4 = HWD / 4;  // 36864

    float s = 0.0f;
    for (int i = threadIdx.x; i < n4; i += 256) {
        float4 v = __ldg(&p4[i]);
        s += (v.x + v.y) + (v.z + v.w);
    }
    #pragma unroll
    for (int o = 16; o; o >>= 1) s += __shfl_down_sync(0xffffffffu, s, o);

    __shared__ float ws[8];
    const int lane = threadIdx.x & 31;
    const int wid  = threadIdx.x >> 5;
    if (lane == 0) ws[wid] = s;
    __syncthreads();
    if (wid == 0) {
        s = (lane < 8) ? ws[lane] : 0.0f;
        #pragma unroll
        for (int o = 4; o; o >>= 1) s += __shfl_down_sync(0xffffffffu, s, o);
        if (lane == 0) g_pooled[plane] = s * (1.0f / (float)HWD);
    }
}

// ---------------------------------------------------------------------------
// Kernel 2: tiny MLP (unchanged, ~noise in the total)
// ---------------------------------------------------------------------------
__global__ __launch_bounds__(256) void mlp_kernel(const float* __restrict__ w1,
                                                  const float* __restrict__ b1,
                                                  const float* __restrict__ w2,
                                                  const float* __restrict__ b2) {
    __shared__ float ps[BB * CC];    // 512
    __shared__ float hs[BB * HID];   // 2048
    const int tid = threadIdx.x;

    for (int i = tid; i < BB * CC; i += 256) ps[i] = g_pooled[i];
    __syncthreads();

    for (int idx = tid; idx < BB * HID; idx += 256) {
        const int b = idx / HID, j = idx % HID;
        float s = b1[j];
        #pragma unroll
        for (int c = 0; c < CC; c++) s += ps[b * CC + c] * w1[c * HID + j];
        hs[idx] = fmaxf(s, 0.0f);
    }
    __syncthreads();

    for (int idx = tid; idx < BB * NOUT; idx += 256) {
        const int b = idx / NOUT, o = idx % NOUT;
        float s = b2[o];
        #pragma unroll 8
        for (int j = 0; j < HID; j++) s += hs[b * HID + j] * w2[j * NOUT + o];
        g_kernels[idx] = s;
    }
}

// ---------------------------------------------------------------------------
// Kernel 3: per-plane dynamic depthwise 3x3, zero padding.
// Block (96,4): tx covers full width (96*4=384) with float4.
// Each thread computes an 8-row x 4-col register tile with a 3-row sliding
// window: 10 row-loads per 8 output rows (halo ratio 1.25x, was 1.5x).
// Output stores use __stcs (evict-first) so the 302 MB write stream does not
// evict the input halo lines from L2.
// ---------------------------------------------------------------------------
#define RPT 8   // rows per thread

__device__ __forceinline__ void load_row6(const float* __restrict__ xp, int r,
                                          int cb, int tx, float a[6]) {
    if (r < 0 || r >= HH) {
        #pragma unroll
        for (int i = 0; i < 6; i++) a[i] = 0.0f;
        return;
    }
    const float* rp = xp + r * WW + cb;
    const float4 c = *reinterpret_cast<const float4*>(rp);
    a[0] = (tx > 0) ? __ldg(rp - 1) : 0.0f;
    a[1] = c.x; a[2] = c.y; a[3] = c.z; a[4] = c.w;
    a[5] = (tx < (WW / 4 - 1)) ? __ldg(rp + 4) : 0.0f;
}

__global__ __launch_bounds__(384) void conv_kernel(const float* __restrict__ x,
                                                   float* __restrict__ out) {
    const int plane = blockIdx.x;                 // b*NK + nk  (C == NK)
    const int tx = threadIdx.x;                   // 0..95
    const int ty = threadIdx.y;                   // 0..3
    const int cb = tx * 4;
    const int r0 = blockIdx.y * (4 * RPT) + ty * RPT;

    const float* xp = x   + (size_t)plane * HWD;
    float*       op = out + (size_t)plane * HWD;

    const float* kw = g_kernels + plane * 9;
    const float w00 = kw[0], w01 = kw[1], w02 = kw[2];
    const float w10 = kw[3], w11 = kw[4], w12 = kw[5];
    const float w20 = kw[6], w21 = kw[7], w22 = kw[8];

    float a0[6], a1[6], a2[6];
    load_row6(xp, r0 - 1, cb, tx, a0);
    load_row6(xp, r0,     cb, tx, a1);

    #pragma unroll
    for (int i = 0; i < RPT; i++) {
        load_row6(xp, r0 + i + 1, cb, tx, a2);

        float4 o;
        o.x = w00 * a0[0] + w01 * a0[1] + w02 * a0[2]
            + w10 * a1[0] + w11 * a1[1] + w12 * a1[2]
            + w20 * a2[0] + w21 * a2[1] + w22 * a2[2];
        o.y = w00 * a0[1] + w01 * a0[2] + w02 * a0[3]
            + w10 * a1[1] + w11 * a1[2] + w12 * a1[3]
            + w20 * a2[1] + w21 * a2[2] + w22 * a2[3];
        o.z = w00 * a0[2] + w01 * a0[3] + w02 * a0[4]
            + w10 * a1[2] + w11 * a1[3] + w12 * a1[4]
            + w20 * a2[2] + w21 * a2[3] + w22 * a2[4];
        o.w = w00 * a0[3] + w01 * a0[4] + w02 * a0[5]
            + w10 * a1[3] + w11 * a1[4] + w12 * a1[5]
            + w20 * a2[3] + w21 * a2[4] + w22 * a2[5];

        __stcs(reinterpret_cast<float4*>(op + (r0 + i) * WW + cb), o);

        #pragma unroll
        for (int k = 0; k < 6; k++) { a0[k] = a1[k]; a1[k] = a2[k]; }
    }
}

// ---------------------------------------------------------------------------
extern "C" void kernel_launch(void* const* d_in, const int* in_sizes, int n_in,
                              void* d_out, int out_size) {
    const float* x  = (const float*)d_in[0];
    const float* w1 = (const float*)d_in[1];
    const float* b1 = (const float*)d_in[2];
    const float* w2 = (const float*)d_in[3];
    const float* b2 = (const float*)d_in[4];
    float* out = (float*)d_out;

    pool_kernel<<<NPLANES, 256>>>(x);
    mlp_kernel<<<1, 256>>>(w1, b1, w2, b2);
    conv_kernel<<<dim3(NPLANES, HH / (4 * RPT)), dim3(96, 4)>>>(x, out);
}